// round 11
// baseline (speedup 1.0000x reference)
#include <cuda_runtime.h>
#include <cuda_bf16.h>
#include <cstdint>
#include <cstddef>

// Problem constants
#define T_STEPS 2048
#define BATCH   256
#define FEAT    64
#define KDIM    320            // FEAT + HID
#define NB      8              // batches per cluster = MMA N
#define THREADS 128
#define LINES   648            // 8 n-rows * 81 lines of 16B per act buffer
#define BUFBYTES (LINES * 16)  // 10368 B per buffer

__device__ __forceinline__ uint32_t s2u(const void* p) {
    uint32_t a;
    asm("{ .reg .u64 t; cvta.to.shared.u64 t, %1; cvt.u32.u64 %0, t; }"
        : "=r"(a) : "l"(p));
    return a;
}
__device__ __forceinline__ uint32_t mapa_rank(uint32_t laddr, uint32_t r) {
    uint32_t o;
    asm("mapa.shared::cluster.u32 %0, %1, %2;" : "=r"(o) : "r"(laddr), "r"(r));
    return o;
}
__device__ __forceinline__ void stc_u16(uint32_t addr, uint16_t v) {
    asm volatile("st.shared::cluster.u16 [%0], %1;" :: "r"(addr), "h"(v) : "memory");
}
__device__ __forceinline__ void redg_add(float* p, float v) {
    asm volatile("red.global.add.f32 [%0], %1;" :: "l"(p), "f"(v) : "memory");
}
__device__ __forceinline__ void hmma(float& d0, float& d1, float& d2, float& d3,
                                     uint32_t a0, uint32_t a1, uint32_t a2, uint32_t a3,
                                     uint32_t b0, uint32_t b1) {
    asm("mma.sync.aligned.m16n8k16.row.col.f32.bf16.bf16.f32 "
        "{%0,%1,%2,%3}, {%4,%5,%6,%7}, {%8,%9}, {%0,%1,%2,%3};"
        : "+f"(d0), "+f"(d1), "+f"(d2), "+f"(d3)
        : "r"(a0), "r"(a1), "r"(a2), "r"(a3), "r"(b0), "r"(b1));
}

__device__ __forceinline__ void split_bf16(float v, uint16_t& hi, uint16_t& lo) {
    __nv_bfloat16 h = __float2bfloat16_rn(v);
    float r = v - __bfloat162float(h);
    hi = __bfloat16_as_ushort(h);
    lo = __bfloat16_as_ushort(__float2bfloat16_rn(r));
}
__device__ __forceinline__ uint32_t pk(uint16_t a, uint16_t b) {
    return (uint32_t)a | ((uint32_t)b << 16);   // a = k-even in low half
}

// ---- init kernel: out[b][t] = bfc (REDG partials accumulate on top) ----
__global__ void init_out_kernel(const float* __restrict__ bfc,
                                float* __restrict__ out) {
    int i = blockIdx.x * blockDim.x + threadIdx.x;
    out[i] = bfc[0];
}

__global__ void __launch_bounds__(THREADS, 1) __cluster_dims__(4, 1, 1)
rnn_hmma_kernel(const float* __restrict__ x,    // (T, B, F)
                const float* __restrict__ W0,   // (H, 320)
                const float* __restrict__ b0,   // (H)
                const float* __restrict__ Wfc,  // (1, H)
                float* __restrict__ out)        // (B, T)
{
    // act buffers: 16B line = {b0_hi, b1_hi, b0_lo, b1_lo} (each b16x2, k-even low)
    __shared__ uint4 buf[2][LINES];

    const int tid  = threadIdx.x;
    const int lane = tid & 31;
    const int wi   = tid >> 5;            // warp 0..3
    const int g    = lane >> 2;           // fragment group 0..7
    const int tq   = lane & 3;            // thread-in-group 0..3

    uint32_t rank;
    asm("mov.u32 %0, %%cluster_ctarank;" : "=r"(rank));
    const int cid = blockIdx.x >> 2;
    const int bg  = cid * NB;

    const int j1 = (int)rank * 64 + wi * 16 + g;   // A rows this thread owns
    const int j2 = j1 + 8;

    // ---- build A fragments (weights, bf16 hi/lo) — 20 chunks x 4 regs each ----
    uint4 ahi[20], alo[20];
    {
        const float* r1 = W0 + (size_t)j1 * KDIM;
        const float* r2 = W0 + (size_t)j2 * KDIM;
        #pragma unroll
        for (int c = 0; c < 20; ++c) {
            int k0 = c * 16 + tq * 2;
            uint16_t h0e,l0e,h0o,l0o,h1e,l1e,h1o,l1o;
            uint16_t h2e,l2e,h2o,l2o,h3e,l3e,h3o,l3o;
            split_bf16(r1[k0],     h0e, l0e); split_bf16(r1[k0 + 1], h0o, l0o);
            split_bf16(r2[k0],     h1e, l1e); split_bf16(r2[k0 + 1], h1o, l1o);
            split_bf16(r1[k0 + 8], h2e, l2e); split_bf16(r1[k0 + 9], h2o, l2o);
            split_bf16(r2[k0 + 8], h3e, l3e); split_bf16(r2[k0 + 9], h3o, l3o);
            ahi[c] = make_uint4(pk(h0e,h0o), pk(h1e,h1o), pk(h2e,h2o), pk(h3e,h3o));
            alo[c] = make_uint4(pk(l0e,l0o), pk(l1e,l1o), pk(l2e,l2o), pk(l3e,l3o));
        }
    }

    const float b0a = b0[j1], b0b = b0[j2];
    const float wf1 = Wfc[j1], wf2 = Wfc[j2];

    // ---- h store geometry: k1 = 64+j1 -> b0 slot; k2 = 64+j2 -> b1 slot ----
    const int c_h  = (64 + j1) >> 4;       // = 4 + rank*4 + wi
    const int t_h  = g >> 1;
    const int slot = (g & 1) * 2;          // byte offset of k parity within b16x2
    const int n0   = tq * 2;
    const int Ln0  = (n0 * 81 + c_h * 4 + t_h) * 16;
    const int Ln1  = ((n0 + 1) * 81 + c_h * 4 + t_h) * 16;

    uint32_t peer[4];
    {
        uint32_t sbuf = s2u(buf);
        #pragma unroll
        for (int r = 0; r < 4; ++r) peer[r] = mapa_rank(sbuf, (uint32_t)r);
    }

    // ---- x deposit geometry: thread owns (n_x, k4..k4+3) ----
    const int n_x = tid >> 4;
    const int k4  = (tid & 15) * 4;
    const int klx = k4 & 15;
    const int b01x = (klx >= 8) ? 4 : 0;          // byte offset of b0 vs b1
    const int t0x  = (klx & 7) >> 1;
    const int xbase = (n_x * 81 + (k4 >> 4) * 4 + t0x) * 16 + b01x;

    // zero both buffers (h region of buf0 must be 0 at t=0)
    for (int i = tid; i < 2 * LINES; i += THREADS)
        (&buf[0][0])[i] = make_uint4(0u, 0u, 0u, 0u);
    __syncthreads();

    // deposit x_0 into buf0; prefetch x_1
    char* const bufc = reinterpret_cast<char*>(buf);
    {
        float4 v = *reinterpret_cast<const float4*>(
            x + ((size_t)0 * BATCH + bg + n_x) * FEAT + k4);
        uint16_t hx,lx,hy,ly,hz,lz,hw,lw;
        split_bf16(v.x,hx,lx); split_bf16(v.y,hy,ly);
        split_bf16(v.z,hz,lz); split_bf16(v.w,hw,lw);
        *reinterpret_cast<uint32_t*>(bufc + xbase)      = pk(hx,hy);
        *reinterpret_cast<uint32_t*>(bufc + xbase + 16) = pk(hz,hw);
        *reinterpret_cast<uint32_t*>(bufc + xbase + 8)  = pk(lx,ly);
        *reinterpret_cast<uint32_t*>(bufc + xbase + 24) = pk(lz,lw);
    }
    float4 xv = *reinterpret_cast<const float4*>(
        x + ((size_t)1 * BATCH + bg + n_x) * FEAT + k4);

    asm volatile("barrier.cluster.arrive.aligned;" ::: "memory");
    asm volatile("barrier.cluster.wait.aligned;"  ::: "memory");

    const int bidx = g * 81 + tq;     // B-fragment line index (n = g, kgroup = tq)

    for (int t = 0; t < T_STEPS; ++t) {
        const int p = t & 1;
        const int q = p ^ 1;

        // ---- 60 HMMAs over 20 k-chunks, 4 rotating accumulator chains ----
        float dacc[16];
        #pragma unroll
        for (int i = 0; i < 16; ++i) dacc[i] = 0.f;

        const uint4* Bb = &buf[p][bidx];
        #pragma unroll
        for (int c = 0; c < 20; ++c) {
            uint4 Bv = Bb[c * 4];
            const int ch = (c & 3) * 4;
            hmma(dacc[ch], dacc[ch+1], dacc[ch+2], dacc[ch+3],
                 ahi[c].x, ahi[c].y, ahi[c].z, ahi[c].w, Bv.x, Bv.y);   // hi*hi
            hmma(dacc[ch], dacc[ch+1], dacc[ch+2], dacc[ch+3],
                 ahi[c].x, ahi[c].y, ahi[c].z, ahi[c].w, Bv.z, Bv.w);   // hi*lo
            hmma(dacc[ch], dacc[ch+1], dacc[ch+2], dacc[ch+3],
                 alo[c].x, alo[c].y, alo[c].z, alo[c].w, Bv.x, Bv.y);   // lo*hi
        }
        float d0 = (dacc[0] + dacc[4]) + (dacc[8]  + dacc[12]);  // (j1, n0)
        float d1 = (dacc[1] + dacc[5]) + (dacc[9]  + dacc[13]);  // (j1, n0+1)
        float d2 = (dacc[2] + dacc[6]) + (dacc[10] + dacc[14]);  // (j2, n0)
        float d3 = (dacc[3] + dacc[7]) + (dacc[11] + dacc[15]);  // (j2, n0+1)

        // ---- tanh (accurate exp identity) ----
        float e00 = __expf(2.f * (d0 + b0a));
        float e01 = __expf(2.f * (d1 + b0a));
        float e10 = __expf(2.f * (d2 + b0b));
        float e11 = __expf(2.f * (d3 + b0b));
        float h00 = 1.f - __fdividef(2.f, e00 + 1.f);
        float h01 = 1.f - __fdividef(2.f, e01 + 1.f);
        float h10 = 1.f - __fdividef(2.f, e10 + 1.f);
        float h11 = 1.f - __fdividef(2.f, e11 + 1.f);

        uint16_t s00h,s00l,s01h,s01l,s10h,s10l,s11h,s11l;
        split_bf16(h00, s00h, s00l); split_bf16(h01, s01h, s01l);
        split_bf16(h10, s10h, s10l); split_bf16(h11, s11h, s11l);

        // ---- broadcast h into next buffer of all 4 cluster CTAs ----
        const uint32_t qoff = (uint32_t)q * BUFBYTES;
        #pragma unroll
        for (int r = 0; r < 4; ++r) {
            const uint32_t base = peer[r] + qoff;
            stc_u16(base + Ln0 + slot,      s00h);   // j1 hi (b0h)
            stc_u16(base + Ln0 + 4 + slot,  s10h);   // j2 hi (b1h)
            stc_u16(base + Ln0 + 8 + slot,  s00l);   // j1 lo (b0l)
            stc_u16(base + Ln0 + 12 + slot, s10l);   // j2 lo (b1l)
            stc_u16(base + Ln1 + slot,      s01h);
            stc_u16(base + Ln1 + 4 + slot,  s11h);
            stc_u16(base + Ln1 + 8 + slot,  s01l);
            stc_u16(base + Ln1 + 12 + slot, s11l);
        }

        // ---- deposit x_{t+1} locally into next buffer ----
        {
            char* bq = bufc + q * BUFBYTES;
            uint16_t hx,lx,hy,ly,hz,lz,hw,lw;
            split_bf16(xv.x,hx,lx); split_bf16(xv.y,hy,ly);
            split_bf16(xv.z,hz,lz); split_bf16(xv.w,hw,lw);
            *reinterpret_cast<uint32_t*>(bq + xbase)      = pk(hx,hy);
            *reinterpret_cast<uint32_t*>(bq + xbase + 16) = pk(hz,hw);
            *reinterpret_cast<uint32_t*>(bq + xbase + 8)  = pk(lx,ly);
            *reinterpret_cast<uint32_t*>(bq + xbase + 24) = pk(lz,lw);
        }

        asm volatile("barrier.cluster.arrive.aligned;" ::: "memory");

        // ---- shadow region ----
        if (t + 2 < T_STEPS)
            xv = *reinterpret_cast<const float4*>(
                x + ((size_t)(t + 2) * BATCH + bg + n_x) * FEAT + k4);

        // output partials: reduce h*Wfc over the 8 j-groups (lane bits 2..4)
        float po0 = h00 * wf1 + h10 * wf2;
        float po1 = h01 * wf1 + h11 * wf2;
        po0 += __shfl_xor_sync(0xffffffffu, po0, 4);
        po1 += __shfl_xor_sync(0xffffffffu, po1, 4);
        po0 += __shfl_xor_sync(0xffffffffu, po0, 8);
        po1 += __shfl_xor_sync(0xffffffffu, po1, 8);
        po0 += __shfl_xor_sync(0xffffffffu, po0, 16);
        po1 += __shfl_xor_sync(0xffffffffu, po1, 16);
        if (g == 0) {
            redg_add(out + (size_t)(bg + n0) * T_STEPS + t,     po0);
            redg_add(out + (size_t)(bg + n0 + 1) * T_STEPS + t, po1);
        }

        asm volatile("barrier.cluster.wait.aligned;" ::: "memory");
    }
}

extern "C" void kernel_launch(void* const* d_in, const int* in_sizes, int n_in,
                              void* d_out, int out_size) {
    const float* x   = (const float*)d_in[0];
    const float* W0  = (const float*)d_in[1];
    const float* b0  = (const float*)d_in[2];
    const float* Wfc = (const float*)d_in[3];
    const float* bfc = (const float*)d_in[4];
    float* out = (float*)d_out;
    (void)in_sizes; (void)n_in; (void)out_size;

    // 1) out[b][t] = bfc
    init_out_kernel<<<(BATCH * T_STEPS) / 256, 256>>>(bfc, out);

    // 2) HMMA RNN: 32 clusters x 4 CTAs, 8 batches/cluster, weights in RF
    rnn_hmma_kernel<<<128, THREADS>>>(x, W0, b0, Wfc, out);
}

// round 12
// speedup vs baseline: 1.5964x; 1.5964x over previous
#include <cuda_runtime.h>
#include <cuda_bf16.h>
#include <cstdint>
#include <cstddef>

// Problem constants
#define T_STEPS 2048
#define BATCH   256
#define FEAT    64
#define KDIM    320            // FEAT + HID
#define NB      8              // batches per cluster = MMA N
#define THREADS 256
#define LINES   648            // 8 n-rows * 81 lines of 16B per act buffer
#define BUFBYTES (LINES * 16)  // 10368 B per buffer

__device__ __forceinline__ uint32_t s2u(const void* p) {
    uint32_t a;
    asm("{ .reg .u64 t; cvta.to.shared.u64 t, %1; cvt.u32.u64 %0, t; }"
        : "=r"(a) : "l"(p));
    return a;
}
__device__ __forceinline__ uint32_t mapa_rank(uint32_t laddr, uint32_t r) {
    uint32_t o;
    asm("mapa.shared::cluster.u32 %0, %1, %2;" : "=r"(o) : "r"(laddr), "r"(r));
    return o;
}
__device__ __forceinline__ void stc_u16(uint32_t addr, uint16_t v) {
    asm volatile("st.shared::cluster.u16 [%0], %1;" :: "r"(addr), "h"(v) : "memory");
}
__device__ __forceinline__ void redg_add(float* p, float v) {
    asm volatile("red.global.add.f32 [%0], %1;" :: "l"(p), "f"(v) : "memory");
}
__device__ __forceinline__ void hmma(float& d0, float& d1, float& d2, float& d3,
                                     uint32_t a0, uint32_t a1, uint32_t a2, uint32_t a3,
                                     uint32_t b0, uint32_t b1) {
    asm("mma.sync.aligned.m16n8k16.row.col.f32.bf16.bf16.f32 "
        "{%0,%1,%2,%3}, {%4,%5,%6,%7}, {%8,%9}, {%0,%1,%2,%3};"
        : "+f"(d0), "+f"(d1), "+f"(d2), "+f"(d3)
        : "r"(a0), "r"(a1), "r"(a2), "r"(a3), "r"(b0), "r"(b1));
}

__device__ __forceinline__ void split_bf16(float v, uint16_t& hi, uint16_t& lo) {
    __nv_bfloat16 h = __float2bfloat16_rn(v);
    float r = v - __bfloat162float(h);
    hi = __bfloat16_as_ushort(h);
    lo = __bfloat16_as_ushort(__float2bfloat16_rn(r));
}
__device__ __forceinline__ uint32_t pk(uint16_t a, uint16_t b) {
    return (uint32_t)a | ((uint32_t)b << 16);   // a = k-even in low half
}

// ---- init kernel: out[b][t] = bfc (REDG partials accumulate on top) ----
__global__ void init_out_kernel(const float* __restrict__ bfc,
                                float* __restrict__ out) {
    int i = blockIdx.x * blockDim.x + threadIdx.x;
    out[i] = bfc[0];
}

__global__ void __launch_bounds__(THREADS, 1) __cluster_dims__(2, 1, 1)
rnn_hmma_kernel(const float* __restrict__ x,    // (T, B, F)
                const float* __restrict__ W0,   // (H, 320)
                const float* __restrict__ b0,   // (H)
                const float* __restrict__ Wfc,  // (1, H)
                float* __restrict__ out)        // (B, T)
{
    // act buffers: 16B line = {b0_hi, b1_hi, b0_lo, b1_lo} (each b16x2, k-even low)
    __shared__ uint4 buf[2][LINES];

    const int tid  = threadIdx.x;
    const int lane = tid & 31;
    const int wi   = tid >> 5;            // warp 0..7
    const int g    = lane >> 2;           // fragment group 0..7
    const int tq   = lane & 3;            // thread-in-group 0..3

    uint32_t rank;
    asm("mov.u32 %0, %%cluster_ctarank;" : "=r"(rank));
    const int cid = blockIdx.x >> 1;
    const int bg  = cid * NB;

    const int j1 = (int)rank * 128 + wi * 16 + g;   // A rows this thread owns
    const int j2 = j1 + 8;

    // ---- build A fragments (weights, bf16 hi/lo) — 20 chunks x 4 regs each ----
    uint4 ahi[20], alo[20];
    {
        const float* r1 = W0 + (size_t)j1 * KDIM;
        const float* r2 = W0 + (size_t)j2 * KDIM;
        #pragma unroll
        for (int c = 0; c < 20; ++c) {
            int k0 = c * 16 + tq * 2;
            uint16_t h0e,l0e,h0o,l0o,h1e,l1e,h1o,l1o;
            uint16_t h2e,l2e,h2o,l2o,h3e,l3e,h3o,l3o;
            split_bf16(r1[k0],     h0e, l0e); split_bf16(r1[k0 + 1], h0o, l0o);
            split_bf16(r2[k0],     h1e, l1e); split_bf16(r2[k0 + 1], h1o, l1o);
            split_bf16(r1[k0 + 8], h2e, l2e); split_bf16(r1[k0 + 9], h2o, l2o);
            split_bf16(r2[k0 + 8], h3e, l3e); split_bf16(r2[k0 + 9], h3o, l3o);
            ahi[c] = make_uint4(pk(h0e,h0o), pk(h1e,h1o), pk(h2e,h2o), pk(h3e,h3o));
            alo[c] = make_uint4(pk(l0e,l0o), pk(l1e,l1o), pk(l2e,l2o), pk(l3e,l3o));
        }
    }

    const float b0a = b0[j1], b0b = b0[j2];
    const float wf1 = Wfc[j1], wf2 = Wfc[j2];

    // ---- h store geometry: k = 64 + j1 -> b0 slot; 64 + j2 -> b1 slot ----
    const int c_h  = (64 + j1) >> 4;       // 4 + rank*8 + wi  (4..19)
    const int t_h  = g >> 1;
    const int slot = (g & 1) * 2;
    const int n0   = tq * 2;
    const int Ln0  = (n0 * 81 + c_h * 4 + t_h) * 16;
    const int Ln1  = ((n0 + 1) * 81 + c_h * 4 + t_h) * 16;

    const uint32_t peer = mapa_rank(s2u(buf), rank ^ 1u);   // peer CTA's buf base

    // ---- x deposit geometry: threads 0..127 own (n_x, k4..k4+3) ----
    const bool xown = tid < 128;
    const int n_x = (tid >> 4) & 7;
    const int k4  = (tid & 15) * 4;
    const int klx = k4 & 15;
    const int b01x = (klx >= 8) ? 4 : 0;
    const int t0x  = (klx & 7) >> 1;
    const int xbase = (n_x * 81 + (k4 >> 4) * 4 + t0x) * 16 + b01x;

    // zero both buffers (h region of buf0 must be 0 at t=0)
    for (int i = tid; i < 2 * LINES; i += THREADS)
        (&buf[0][0])[i] = make_uint4(0u, 0u, 0u, 0u);
    __syncthreads();

    // deposit x_0 into buf0; prefetch x_1
    char* const bufc = reinterpret_cast<char*>(buf);
    float4 xv = make_float4(0.f, 0.f, 0.f, 0.f);
    if (xown) {
        float4 v = *reinterpret_cast<const float4*>(
            x + ((size_t)0 * BATCH + bg + n_x) * FEAT + k4);
        uint16_t hx,lx,hy,ly,hz,lz,hw,lw;
        split_bf16(v.x,hx,lx); split_bf16(v.y,hy,ly);
        split_bf16(v.z,hz,lz); split_bf16(v.w,hw,lw);
        *reinterpret_cast<uint32_t*>(bufc + xbase)      = pk(hx,hy);
        *reinterpret_cast<uint32_t*>(bufc + xbase + 16) = pk(hz,hw);
        *reinterpret_cast<uint32_t*>(bufc + xbase + 8)  = pk(lx,ly);
        *reinterpret_cast<uint32_t*>(bufc + xbase + 24) = pk(lz,lw);
        xv = *reinterpret_cast<const float4*>(
            x + ((size_t)1 * BATCH + bg + n_x) * FEAT + k4);
    }

    asm volatile("barrier.cluster.arrive.aligned;" ::: "memory");
    asm volatile("barrier.cluster.wait.aligned;"  ::: "memory");

    const int bidx = g * 81 + tq;     // B-fragment line index (n = g, kgroup = tq)

    for (int t = 0; t < T_STEPS; ++t) {
        const int p = t & 1;
        const int q = p ^ 1;

        // ---- 60 HMMAs over 20 k-chunks, 4 rotating accumulator chains ----
        float dacc[16];
        #pragma unroll
        for (int i = 0; i < 16; ++i) dacc[i] = 0.f;

        const uint4* Bb = &buf[p][bidx];
        #pragma unroll
        for (int c = 0; c < 20; ++c) {
            uint4 Bv = Bb[c * 4];
            const int ch = (c & 3) * 4;
            hmma(dacc[ch], dacc[ch+1], dacc[ch+2], dacc[ch+3],
                 ahi[c].x, ahi[c].y, ahi[c].z, ahi[c].w, Bv.x, Bv.y);   // hi*hi
            hmma(dacc[ch], dacc[ch+1], dacc[ch+2], dacc[ch+3],
                 ahi[c].x, ahi[c].y, ahi[c].z, ahi[c].w, Bv.z, Bv.w);   // hi*lo
            hmma(dacc[ch], dacc[ch+1], dacc[ch+2], dacc[ch+3],
                 alo[c].x, alo[c].y, alo[c].z, alo[c].w, Bv.x, Bv.y);   // lo*hi
        }
        float d0 = (dacc[0] + dacc[4]) + (dacc[8]  + dacc[12]);  // (j1, n0)
        float d1 = (dacc[1] + dacc[5]) + (dacc[9]  + dacc[13]);  // (j1, n0+1)
        float d2 = (dacc[2] + dacc[6]) + (dacc[10] + dacc[14]);  // (j2, n0)
        float d3 = (dacc[3] + dacc[7]) + (dacc[11] + dacc[15]);  // (j2, n0+1)

        // ---- tanh (accurate exp identity) ----
        float e00 = __expf(2.f * (d0 + b0a));
        float e01 = __expf(2.f * (d1 + b0a));
        float e10 = __expf(2.f * (d2 + b0b));
        float e11 = __expf(2.f * (d3 + b0b));
        float h00 = 1.f - __fdividef(2.f, e00 + 1.f);
        float h01 = 1.f - __fdividef(2.f, e01 + 1.f);
        float h10 = 1.f - __fdividef(2.f, e10 + 1.f);
        float h11 = 1.f - __fdividef(2.f, e11 + 1.f);

        uint16_t s00h,s00l,s01h,s01l,s10h,s10l,s11h,s11l;
        split_bf16(h00, s00h, s00l); split_bf16(h01, s01h, s01l);
        split_bf16(h10, s10h, s10l); split_bf16(h11, s11h, s11l);

        // ---- write h into next buffer: local STS + one DSMEM peer ----
        const uint32_t qoff = (uint32_t)q * BUFBYTES;
        {
            char* lb = bufc + qoff;
            *reinterpret_cast<uint16_t*>(lb + Ln0 + slot)      = s00h;
            *reinterpret_cast<uint16_t*>(lb + Ln0 + 4 + slot)  = s10h;
            *reinterpret_cast<uint16_t*>(lb + Ln0 + 8 + slot)  = s00l;
            *reinterpret_cast<uint16_t*>(lb + Ln0 + 12 + slot) = s10l;
            *reinterpret_cast<uint16_t*>(lb + Ln1 + slot)      = s01h;
            *reinterpret_cast<uint16_t*>(lb + Ln1 + 4 + slot)  = s11h;
            *reinterpret_cast<uint16_t*>(lb + Ln1 + 8 + slot)  = s01l;
            *reinterpret_cast<uint16_t*>(lb + Ln1 + 12 + slot) = s11l;

            const uint32_t rb = peer + qoff;
            stc_u16(rb + Ln0 + slot,      s00h);
            stc_u16(rb + Ln0 + 4 + slot,  s10h);
            stc_u16(rb + Ln0 + 8 + slot,  s00l);
            stc_u16(rb + Ln0 + 12 + slot, s10l);
            stc_u16(rb + Ln1 + slot,      s01h);
            stc_u16(rb + Ln1 + 4 + slot,  s11h);
            stc_u16(rb + Ln1 + 8 + slot,  s01l);
            stc_u16(rb + Ln1 + 12 + slot, s11l);
        }

        // ---- deposit x_{t+1} locally into next buffer ----
        if (xown) {
            char* bq = bufc + qoff;
            uint16_t hx,lx,hy,ly,hz,lz,hw,lw;
            split_bf16(xv.x,hx,lx); split_bf16(xv.y,hy,ly);
            split_bf16(xv.z,hz,lz); split_bf16(xv.w,hw,lw);
            *reinterpret_cast<uint32_t*>(bq + xbase)      = pk(hx,hy);
            *reinterpret_cast<uint32_t*>(bq + xbase + 16) = pk(hz,hw);
            *reinterpret_cast<uint32_t*>(bq + xbase + 8)  = pk(lx,ly);
            *reinterpret_cast<uint32_t*>(bq + xbase + 24) = pk(lz,lw);
        }

        asm volatile("barrier.cluster.arrive.aligned;" ::: "memory");

        // ---- shadow region ----
        if (xown && (t + 2) < T_STEPS)
            xv = *reinterpret_cast<const float4*>(
                x + ((size_t)(t + 2) * BATCH + bg + n_x) * FEAT + k4);

        // output partials: reduce h*Wfc over the 8 j-groups (lane bits 2..4)
        float po0 = h00 * wf1 + h10 * wf2;
        float po1 = h01 * wf1 + h11 * wf2;
        po0 += __shfl_xor_sync(0xffffffffu, po0, 4);
        po1 += __shfl_xor_sync(0xffffffffu, po1, 4);
        po0 += __shfl_xor_sync(0xffffffffu, po0, 8);
        po1 += __shfl_xor_sync(0xffffffffu, po1, 8);
        po0 += __shfl_xor_sync(0xffffffffu, po0, 16);
        po1 += __shfl_xor_sync(0xffffffffu, po1, 16);
        if (g == 0) {
            redg_add(out + (size_t)(bg + n0) * T_STEPS + t,     po0);
            redg_add(out + (size_t)(bg + n0 + 1) * T_STEPS + t, po1);
        }

        asm volatile("barrier.cluster.wait.aligned;" ::: "memory");
    }
}

extern "C" void kernel_launch(void* const* d_in, const int* in_sizes, int n_in,
                              void* d_out, int out_size) {
    const float* x   = (const float*)d_in[0];
    const float* W0  = (const float*)d_in[1];
    const float* b0  = (const float*)d_in[2];
    const float* Wfc = (const float*)d_in[3];
    const float* bfc = (const float*)d_in[4];
    float* out = (float*)d_out;
    (void)in_sizes; (void)n_in; (void)out_size;

    // 1) out[b][t] = bfc
    init_out_kernel<<<(BATCH * T_STEPS) / 256, 256>>>(bfc, out);

    // 2) HMMA RNN: 32 clusters x 2 CTAs x 256 thr, 8 batches/cluster, weights in RF
    rnn_hmma_kernel<<<64, THREADS>>>(x, W0, b0, Wfc, out);
}

// round 13
// speedup vs baseline: 4.2699x; 2.6747x over previous
#include <cuda_runtime.h>
#include <cuda_fp16.h>
#include <cstdint>
#include <cstddef>

// Problem constants
#define T_STEPS 2048
#define BATCH   256
#define FEAT    64
#define KDIM    320            // FEAT + HID
#define NB      8              // batches per CTA = MMA N
#define THREADS 512
#define NC      20             // k-chunks of 16
#define ROWW    168            // words per n-row (160 data + 8 pad -> conflict-free LDS.64)
#define ROWB    (ROWW * 4)     // 672 bytes
#define BUFW    (NB * ROWW)    // 1344 words per buffer
#define BUFB    (BUFW * 4)     // 5376 bytes

__device__ __forceinline__ void redg_add(float* p, float v) {
    asm volatile("red.global.add.f32 [%0], %1;" :: "l"(p), "f"(v) : "memory");
}
__device__ __forceinline__ void hmma_fp16(float& d0, float& d1, float& d2, float& d3,
                                          uint32_t a0, uint32_t a1, uint32_t a2, uint32_t a3,
                                          uint32_t b0, uint32_t b1) {
    asm("mma.sync.aligned.m16n8k16.row.col.f32.f16.f16.f32 "
        "{%0,%1,%2,%3}, {%4,%5,%6,%7}, {%8,%9}, {%0,%1,%2,%3};"
        : "+f"(d0), "+f"(d1), "+f"(d2), "+f"(d3)
        : "r"(a0), "r"(a1), "r"(a2), "r"(a3), "r"(b0), "r"(b1));
}
__device__ __forceinline__ uint16_t f2h(float v) {
    return __half_as_ushort(__float2half_rn(v));
}
__device__ __forceinline__ uint32_t pk(uint16_t a, uint16_t b) {
    return (uint32_t)a | ((uint32_t)b << 16);   // a = k-even in low half
}

// ---- init kernel: out[b][t] = bfc (REDG partials accumulate on top) ----
__global__ void init_out_kernel(const float* __restrict__ bfc,
                                float* __restrict__ out) {
    int i = blockIdx.x * blockDim.x + threadIdx.x;
    out[i] = bfc[0];
}

__global__ void __launch_bounds__(THREADS, 1)
rnn_hmma_kernel(const float* __restrict__ x,    // (T, B, F)
                const float* __restrict__ W0,   // (H, 320)
                const float* __restrict__ b0,   // (H)
                const float* __restrict__ Wfc,  // (1, H)
                float* __restrict__ out)        // (B, T)
{
    // fp16 act buffers: per n-row, chunk c, subline t (8B) = {kpair(2t), kpair(2t)+8}
    __shared__ uint32_t buf[2][BUFW];

    const int tid  = threadIdx.x;
    const int lane = tid & 31;
    const int wi   = tid >> 5;            // warp 0..15 — owns j in [wi*16, wi*16+16)
    const int g    = lane >> 2;           // fragment group 0..7
    const int tq   = lane & 3;            // thread-in-group 0..3
    const int bg   = blockIdx.x * NB;     // first batch of this CTA

    const int j1 = wi * 16 + g;           // A rows this thread owns
    const int j2 = j1 + 8;

    // ---- A fragments (full W0 in RF as fp16): 20 chunks x 4 regs ----
    uint4 afr[NC];
    {
        const float* r1 = W0 + (size_t)j1 * KDIM;
        const float* r2 = W0 + (size_t)j2 * KDIM;
        #pragma unroll
        for (int c = 0; c < NC; ++c) {
            int k0 = c * 16 + tq * 2;
            afr[c] = make_uint4(
                pk(f2h(r1[k0]),     f2h(r1[k0 + 1])),
                pk(f2h(r2[k0]),     f2h(r2[k0 + 1])),
                pk(f2h(r1[k0 + 8]), f2h(r1[k0 + 9])),
                pk(f2h(r2[k0 + 8]), f2h(r2[k0 + 9])));
        }
    }

    const float b0a = b0[j1], b0b = b0[j2];
    const float wf1 = Wfc[j1], wf2 = Wfc[j2];

    // ---- h store geometry: k1 = 64 + j1 (b0 slot), k2 = 64 + j2 (b1 slot) ----
    // chunk c_h = 4 + wi, subline t = g>>1, byte-in-u32 = (g&1)*2
    const int n0 = tq * 2;
    const int hbyte0 = n0 * ROWB + (4 + wi) * 32 + (g >> 1) * 8 + (g & 1) * 2;
    const int hbyte1 = hbyte0 + ROWB;      // n0+1

    // ---- x deposit geometry: threads 0..127 own (n_x, k4..k4+3) ----
    const bool xown = tid < 128;
    const int n_x = tid >> 4;              // 0..7
    const int k4  = (tid & 15) * 4;        // 0..60
    const int c_x = k4 >> 4;
    const int klx = k4 & 15;
    const int t0x = (klx & 7) >> 1;
    const int offx = (klx >= 8) ? 4 : 0;
    const int xbyte = n_x * ROWB + c_x * 32 + t0x * 8 + offx;

    // zero both buffers (h region of buf0 must be 0 at t=0)
    for (int i = tid; i < 2 * BUFW; i += THREADS) (&buf[0][0])[i] = 0u;
    __syncthreads();

    char* const bufc = reinterpret_cast<char*>(buf);
    float4 xv = make_float4(0.f, 0.f, 0.f, 0.f);
    if (xown) {
        float4 v = *reinterpret_cast<const float4*>(
            x + ((size_t)0 * BATCH + bg + n_x) * FEAT + k4);
        *reinterpret_cast<uint32_t*>(bufc + xbyte)     = pk(f2h(v.x), f2h(v.y));
        *reinterpret_cast<uint32_t*>(bufc + xbyte + 8) = pk(f2h(v.z), f2h(v.w));
        xv = *reinterpret_cast<const float4*>(
            x + ((size_t)1 * BATCH + bg + n_x) * FEAT + k4);
    }
    __syncthreads();

    // B-frag base (uint2 index): line (n = g, chunk c, subline tq)
    const int bbase = g * (ROWW / 2) + tq;     // uint2 units: ROWW/2 = 84 per n

    for (int t = 0; t < T_STEPS; ++t) {
        const int p = t & 1;
        const int q = p ^ 1;

        // ---- 20 HMMAs, 4 rotating accumulator chains ----
        float dacc[16];
        #pragma unroll
        for (int i = 0; i < 16; ++i) dacc[i] = 0.f;

        const uint2* Bb = reinterpret_cast<const uint2*>(buf[p]) + bbase;
        #pragma unroll
        for (int c = 0; c < NC; ++c) {
            uint2 Bv = Bb[c * 4];              // {b0, b1} for this (g, tq, c)
            const int ch = (c & 3) * 4;
            hmma_fp16(dacc[ch], dacc[ch+1], dacc[ch+2], dacc[ch+3],
                      afr[c].x, afr[c].y, afr[c].z, afr[c].w, Bv.x, Bv.y);
        }
        float d0 = (dacc[0] + dacc[4]) + (dacc[8]  + dacc[12]);  // (j1, n0)
        float d1 = (dacc[1] + dacc[5]) + (dacc[9]  + dacc[13]);  // (j1, n0+1)
        float d2 = (dacc[2] + dacc[6]) + (dacc[10] + dacc[14]);  // (j2, n0)
        float d3 = (dacc[3] + dacc[7]) + (dacc[11] + dacc[15]);  // (j2, n0+1)

        // ---- tanh (accurate exp identity) ----
        float e00 = __expf(2.f * (d0 + b0a));
        float e01 = __expf(2.f * (d1 + b0a));
        float e10 = __expf(2.f * (d2 + b0b));
        float e11 = __expf(2.f * (d3 + b0b));
        float h00 = 1.f - __fdividef(2.f, e00 + 1.f);
        float h01 = 1.f - __fdividef(2.f, e01 + 1.f);
        float h10 = 1.f - __fdividef(2.f, e10 + 1.f);
        float h11 = 1.f - __fdividef(2.f, e11 + 1.f);

        // ---- write h (fp16) into next buffer — all local ----
        {
            char* bq = bufc + q * BUFB;
            *reinterpret_cast<uint16_t*>(bq + hbyte0)     = f2h(h00);  // (j1, n0)
            *reinterpret_cast<uint16_t*>(bq + hbyte0 + 4) = f2h(h10);  // (j2, n0)
            *reinterpret_cast<uint16_t*>(bq + hbyte1)     = f2h(h01);  // (j1, n0+1)
            *reinterpret_cast<uint16_t*>(bq + hbyte1 + 4) = f2h(h11);  // (j2, n0+1)
        }

        // ---- deposit x_{t+1} into next buffer ----
        if (xown) {
            char* bq = bufc + q * BUFB;
            *reinterpret_cast<uint32_t*>(bq + xbyte)     = pk(f2h(xv.x), f2h(xv.y));
            *reinterpret_cast<uint32_t*>(bq + xbyte + 8) = pk(f2h(xv.z), f2h(xv.w));
            if (t + 2 < T_STEPS)
                xv = *reinterpret_cast<const float4*>(
                    x + ((size_t)(t + 2) * BATCH + bg + n_x) * FEAT + k4);
        }

        // ---- output partials: reduce h*Wfc over the 8 j-groups, then REDG ----
        float po0 = h00 * wf1 + h10 * wf2;
        float po1 = h01 * wf1 + h11 * wf2;
        po0 += __shfl_xor_sync(0xffffffffu, po0, 4);
        po1 += __shfl_xor_sync(0xffffffffu, po1, 4);
        po0 += __shfl_xor_sync(0xffffffffu, po0, 8);
        po1 += __shfl_xor_sync(0xffffffffu, po1, 8);
        po0 += __shfl_xor_sync(0xffffffffu, po0, 16);
        po1 += __shfl_xor_sync(0xffffffffu, po1, 16);
        if (g == 0) {
            redg_add(out + (size_t)(bg + n0) * T_STEPS + t,     po0);
            redg_add(out + (size_t)(bg + n0 + 1) * T_STEPS + t, po1);
        }

        __syncthreads();   // single barrier per step (double buffer covers both hazards)
    }
}

extern "C" void kernel_launch(void* const* d_in, const int* in_sizes, int n_in,
                              void* d_out, int out_size) {
    const float* x   = (const float*)d_in[0];
    const float* W0  = (const float*)d_in[1];
    const float* b0  = (const float*)d_in[2];
    const float* Wfc = (const float*)d_in[3];
    const float* bfc = (const float*)d_in[4];
    float* out = (float*)d_out;
    (void)in_sizes; (void)n_in; (void)out_size;

    // 1) out[b][t] = bfc
    init_out_kernel<<<(BATCH * T_STEPS) / 256, 256>>>(bfc, out);

    // 2) single-CTA-per-8-batches HMMA RNN: 32 CTAs, 512 thr, full W0 in RF (fp16)
    rnn_hmma_kernel<<<BATCH / NB, THREADS>>>(x, W0, b0, Wfc, out);
}